// round 1
// baseline (speedup 1.0000x reference)
#include <cuda_runtime.h>

#define NHEADS 12
#define HD 64
#define NB 16
#define SEQ 577
#define DIM 768
#define MROWS (NB * SEQ)        // 9232
#define ATT_SCALE 0.125f        // 64^-0.5
#define EPSF 1e-6f

// Scratch (no allocations allowed): qkv in [3, B, H, N, 64], attn out in [B, N, 768]
__device__ float g_qkv[(size_t)3 * NB * NHEADS * SEQ * HD];
__device__ float g_attn[(size_t)NB * SEQ * DIM];

// ---------------------------------------------------------------------------
// QKV GEMM: C[9232, 2304] = x @ Wqkv + bqkv, scattered into [3,B,H,N,64]
// 64x64 tile, 256 threads, 4x4 per thread, K-tile = 16
// ---------------------------------------------------------------------------
__global__ __launch_bounds__(256) void qkv_gemm(const float* __restrict__ A,
                                                const float* __restrict__ W,
                                                const float* __restrict__ bias) {
    __shared__ float As[64 * 16];
    __shared__ float Bs[16 * 64];
    const int bm = blockIdx.y * 64, bn = blockIdx.x * 64;
    const int tid = threadIdx.x;
    const int tx = tid & 15, ty = tid >> 4;

    float acc[4][4] = {};
    for (int k0 = 0; k0 < DIM; k0 += 16) {
        {   // A tile: 64 rows x 16 cols (float4 per thread)
            int r = tid >> 2, c4 = tid & 3;
            float4 v = make_float4(0.f, 0.f, 0.f, 0.f);
            if (bm + r < MROWS)
                v = *(const float4*)(A + (size_t)(bm + r) * DIM + k0 + c4 * 4);
            *(float4*)(As + r * 16 + c4 * 4) = v;
        }
        {   // B tile: 16 rows x 64 cols
            int r = tid >> 4, c4 = tid & 15;
            float4 v = *(const float4*)(W + (size_t)(k0 + r) * (3 * DIM) + bn + c4 * 4);
            *(float4*)(Bs + r * 64 + c4 * 4) = v;
        }
        __syncthreads();
#pragma unroll
        for (int kk = 0; kk < 16; kk++) {
            float a[4], b[4];
#pragma unroll
            for (int i = 0; i < 4; i++) a[i] = As[(4 * ty + i) * 16 + kk];
#pragma unroll
            for (int j = 0; j < 4; j++) b[j] = Bs[kk * 64 + 4 * tx + j];
#pragma unroll
            for (int i = 0; i < 4; i++)
#pragma unroll
                for (int j = 0; j < 4; j++) acc[i][j] += a[i] * b[j];
        }
        __syncthreads();
    }
#pragma unroll
    for (int i = 0; i < 4; i++) {
        int row = bm + 4 * ty + i;
        if (row >= MROWS) continue;
        int b_ = row / SEQ, n = row % SEQ;
#pragma unroll
        for (int j = 0; j < 4; j++) {
            int col = bn + 4 * tx + j;
            float v = acc[i][j] + bias[col];
            int s = col / DIM;
            int rem = col - s * DIM;
            int h = rem >> 6, d = rem & 63;
            g_qkv[(((size_t)s * NB * NHEADS + b_ * NHEADS + h) * SEQ + n) * HD + d] = v;
        }
    }
}

// ---------------------------------------------------------------------------
// Flash-style attention with policy-masked softmax.
// Grid: (ceil(577/64)=10, B*H=192). 256 threads. Dynamic smem ~49.9 KB.
// out_n = (sum_m e_m v_m + (EPS/N) * sum_m v_m) / (sum_m e_m + EPS)
// with e_m = exp(logit - global_max) * keep(m), keep = policy[m] || m==n.
// Max is over RAW logits (pre-mask), matching the reference.
// ---------------------------------------------------------------------------
__global__ __launch_bounds__(256) void attn_kernel(const float* __restrict__ policy) {
    extern __shared__ float sm[];
    float* Qs   = sm;                 // 64 x 64
    float* Vs   = sm + 4096;          // 64 x 64
    float* KPs  = sm + 8192;          // 64 x 65 (K chunk, then reused for P)
    float* vsum = sm + 8192 + 4160;   // 64
    float* pol  = vsum + 64;          // 64

    const int bh = blockIdx.y;
    const int b_ = bh / NHEADS, h = bh % NHEADS;
    const int q0 = blockIdx.x * 64;
    const float* Qg = g_qkv + (size_t)bh * SEQ * HD;
    const float* Kg = g_qkv + (size_t)(NB * NHEADS + bh) * SEQ * HD;
    const float* Vg = g_qkv + (size_t)(2 * NB * NHEADS + bh) * SEQ * HD;
    const int tid = threadIdx.x;
    const int tx = tid & 15, ty = tid >> 4;

    for (int e = tid; e < 64 * 16; e += 256) {
        int r = e >> 4, c4 = e & 15;
        float4 v = make_float4(0.f, 0.f, 0.f, 0.f);
        if (q0 + r < SEQ) v = *(const float4*)(Qg + (size_t)(q0 + r) * HD + c4 * 4);
        *(float4*)(Qs + r * 64 + c4 * 4) = v;
    }
    if (tid < 64) vsum[tid] = 0.f;

    float mrow[4], lrow[4], Oacc[4][4];
#pragma unroll
    for (int i = 0; i < 4; i++) {
        mrow[i] = -1e30f; lrow[i] = 0.f;
#pragma unroll
        for (int j = 0; j < 4; j++) Oacc[i][j] = 0.f;
    }

    for (int kc = 0; kc < 10; kc++) {
        const int kb = kc * 64;
        __syncthreads();  // previous iteration done reading KPs/Vs
        for (int e = tid; e < 64 * 16; e += 256) {
            int r = e >> 4, c4 = e & 15;
            float4 kv = make_float4(0.f, 0.f, 0.f, 0.f), vv = kv;
            if (kb + r < SEQ) {
                kv = *(const float4*)(Kg + (size_t)(kb + r) * HD + c4 * 4);
                vv = *(const float4*)(Vg + (size_t)(kb + r) * HD + c4 * 4);
            }
            float* kd = KPs + r * 65 + c4 * 4;
            kd[0] = kv.x; kd[1] = kv.y; kd[2] = kv.z; kd[3] = kv.w;
            *(float4*)(Vs + r * 64 + c4 * 4) = vv;
        }
        if (tid < 64) pol[tid] = (kb + tid < SEQ) ? policy[b_ * SEQ + kb + tid] : 0.f;
        __syncthreads();

        if (tid < 64) {   // running sum_m v_m[d]  (pad keys loaded as zeros)
            float s = 0.f;
            for (int c = 0; c < 64; c++) s += Vs[c * 64 + tid];
            vsum[tid] += s;
        }

        // S = Q K^T
        float sc[4][4];
#pragma unroll
        for (int i = 0; i < 4; i++)
#pragma unroll
            for (int j = 0; j < 4; j++) sc[i][j] = 0.f;
        for (int d = 0; d < HD; d++) {
            float qa[4], kk[4];
#pragma unroll
            for (int i = 0; i < 4; i++) qa[i] = Qs[(4 * ty + i) * 64 + d];
#pragma unroll
            for (int j = 0; j < 4; j++) kk[j] = KPs[(4 * tx + j) * 65 + d];
#pragma unroll
            for (int i = 0; i < 4; i++)
#pragma unroll
                for (int j = 0; j < 4; j++) sc[i][j] += qa[i] * kk[j];
        }
#pragma unroll
        for (int i = 0; i < 4; i++)
#pragma unroll
            for (int j = 0; j < 4; j++) {
                int key = kb + 4 * tx + j;
                sc[i][j] = (key < SEQ) ? sc[i][j] * ATT_SCALE : -1e30f;
            }

        // online softmax update
#pragma unroll
        for (int i = 0; i < 4; i++) {
            float rm = fmaxf(fmaxf(sc[i][0], sc[i][1]), fmaxf(sc[i][2], sc[i][3]));
#pragma unroll
            for (int off = 8; off; off >>= 1)
                rm = fmaxf(rm, __shfl_xor_sync(0xffffffffu, rm, off, 16));
            float nm = fmaxf(mrow[i], rm);
            float corr = __expf(mrow[i] - nm);
            mrow[i] = nm;
            int q = q0 + 4 * ty + i;
            float ls = 0.f;
#pragma unroll
            for (int j = 0; j < 4; j++) {
                int key = kb + 4 * tx + j;
                bool keep = (key < SEQ) && ((pol[4 * tx + j] > 0.5f) || (key == q));
                float p = keep ? __expf(sc[i][j] - nm) : 0.f;
                sc[i][j] = p;
                ls += p;
            }
#pragma unroll
            for (int off = 8; off; off >>= 1)
                ls += __shfl_xor_sync(0xffffffffu, ls, off, 16);
            lrow[i] = lrow[i] * corr + ls;
#pragma unroll
            for (int j = 0; j < 4; j++) Oacc[i][j] *= corr;
        }
        __syncthreads();  // done reading KPs as K
#pragma unroll
        for (int i = 0; i < 4; i++)
#pragma unroll
            for (int j = 0; j < 4; j++)
                KPs[(4 * ty + i) * 65 + 4 * tx + j] = sc[i][j];
        __syncthreads();

        // O += P @ V
        for (int c = 0; c < 64; c++) {
            float pa[4], vb[4];
#pragma unroll
            for (int i = 0; i < 4; i++) pa[i] = KPs[(4 * ty + i) * 65 + c];
#pragma unroll
            for (int j = 0; j < 4; j++) vb[j] = Vs[c * 64 + 4 * tx + j];
#pragma unroll
            for (int i = 0; i < 4; i++)
#pragma unroll
                for (int j = 0; j < 4; j++) Oacc[i][j] += pa[i] * vb[j];
        }
    }
    __syncthreads();

    const float epsn = EPSF / (float)SEQ;
#pragma unroll
    for (int i = 0; i < 4; i++) {
        int n = q0 + 4 * ty + i;
        if (n >= SEQ) continue;
        float inv = 1.f / (lrow[i] + EPSF);
#pragma unroll
        for (int j = 0; j < 4; j++) {
            int d = 4 * tx + j;
            g_attn[((size_t)b_ * SEQ + n) * DIM + h * HD + d] =
                (Oacc[i][j] + epsn * vsum[d]) * inv;
        }
    }
}

// ---------------------------------------------------------------------------
// Output projection: out[9232, 768] = g_attn @ Wproj + bproj
// ---------------------------------------------------------------------------
__global__ __launch_bounds__(256) void proj_gemm(const float* __restrict__ W,
                                                 const float* __restrict__ bias,
                                                 float* __restrict__ out) {
    __shared__ float As[64 * 16];
    __shared__ float Bs[16 * 64];
    const int bm = blockIdx.y * 64, bn = blockIdx.x * 64;
    const int tid = threadIdx.x;
    const int tx = tid & 15, ty = tid >> 4;

    float acc[4][4] = {};
    for (int k0 = 0; k0 < DIM; k0 += 16) {
        {
            int r = tid >> 2, c4 = tid & 3;
            float4 v = make_float4(0.f, 0.f, 0.f, 0.f);
            if (bm + r < MROWS)
                v = *(const float4*)(g_attn + (size_t)(bm + r) * DIM + k0 + c4 * 4);
            *(float4*)(As + r * 16 + c4 * 4) = v;
        }
        {
            int r = tid >> 4, c4 = tid & 15;
            float4 v = *(const float4*)(W + (size_t)(k0 + r) * DIM + bn + c4 * 4);
            *(float4*)(Bs + r * 64 + c4 * 4) = v;
        }
        __syncthreads();
#pragma unroll
        for (int kk = 0; kk < 16; kk++) {
            float a[4], b[4];
#pragma unroll
            for (int i = 0; i < 4; i++) a[i] = As[(4 * ty + i) * 16 + kk];
#pragma unroll
            for (int j = 0; j < 4; j++) b[j] = Bs[kk * 64 + 4 * tx + j];
#pragma unroll
            for (int i = 0; i < 4; i++)
#pragma unroll
                for (int j = 0; j < 4; j++) acc[i][j] += a[i] * b[j];
        }
        __syncthreads();
    }
#pragma unroll
    for (int i = 0; i < 4; i++) {
        int row = bm + 4 * ty + i;
        if (row >= MROWS) continue;
#pragma unroll
        for (int j = 0; j < 4; j++) {
            int col = bn + 4 * tx + j;
            out[(size_t)row * DIM + col] = acc[i][j] + bias[col];
        }
    }
}

extern "C" void kernel_launch(void* const* d_in, const int* in_sizes, int n_in,
                              void* d_out, int out_size) {
    const float* x      = (const float*)d_in[0];
    const float* policy = (const float*)d_in[1];
    const float* Wqkv   = (const float*)d_in[2];
    const float* bqkv   = (const float*)d_in[3];
    const float* Wproj  = (const float*)d_in[4];
    const float* bproj  = (const float*)d_in[5];
    float* out = (float*)d_out;

    (void)in_sizes; (void)n_in; (void)out_size;

    // 1) QKV projection + scatter
    dim3 g1((3 * DIM) / 64, (MROWS + 63) / 64);
    qkv_gemm<<<g1, 256>>>(x, Wqkv, bqkv);

    // 2) policy-masked flash attention
    const int smem = (4096 + 4096 + 4160 + 64 + 64) * 4;  // 49920 B
    cudaFuncSetAttribute(attn_kernel, cudaFuncAttributeMaxDynamicSharedMemorySize, smem);
    dim3 g2((SEQ + 63) / 64, NB * NHEADS);
    attn_kernel<<<g2, 256, smem>>>(policy);

    // 3) output projection
    dim3 g3(DIM / 64, (MROWS + 63) / 64);
    proj_gemm<<<g3, 256>>>(Wproj, bproj, out);
}

// round 3
// speedup vs baseline: 1.6738x; 1.6738x over previous
#include <cuda_runtime.h>
#include <cstdint>

#define NHEADS 12
#define HD 64
#define NB 16
#define SEQ 577
#define DIM 768
#define MROWS (NB * SEQ)        // 9232
#define NQKV (3 * DIM)          // 2304
#define ATT_SCALE 0.125f
#define EPSF 1e-6f
#define AST 36                  // smem row stride (floats), conflict-free & float4-aligned

// Scratch (no allocations allowed)
__device__ float g_qkv[(size_t)3 * NB * NHEADS * SEQ * HD];   // [3,B,H,N,64]
__device__ float g_attn[(size_t)MROWS * DIM];                 // [B*N, 768]
__device__ float g_wqkv_t[(size_t)NQKV * DIM];                // [2304, 768] = Wqkv^T
__device__ float g_wproj_t[(size_t)DIM * DIM];                // [768, 768]  = Wproj^T

__device__ __forceinline__ uint32_t f2tf32(float x) {
    uint32_t r;
    asm("cvt.rna.tf32.f32 %0, %1;" : "=r"(r) : "f"(x));
    return r;
}
__device__ __forceinline__ void mma1688(float d[4], const uint32_t a[4], const uint32_t b[2]) {
    asm volatile(
        "mma.sync.aligned.m16n8k8.row.col.f32.tf32.tf32.f32 "
        "{%0,%1,%2,%3}, {%4,%5,%6,%7}, {%8,%9}, {%0,%1,%2,%3};"
        : "+f"(d[0]), "+f"(d[1]), "+f"(d[2]), "+f"(d[3])
        : "r"(a[0]), "r"(a[1]), "r"(a[2]), "r"(a[3]), "r"(b[0]), "r"(b[1]));
}

// ---------------------------------------------------------------------------
// Weight transpose: Wt[n][k] = W[k][n].
// ---------------------------------------------------------------------------
__global__ __launch_bounds__(256) void transpose_w(const float* __restrict__ W,
                                                   float* __restrict__ Wt,
                                                   int Kdim, int Ncols) {
    __shared__ float t[32][33];
    const int n0 = blockIdx.x * 32, k0 = blockIdx.y * 32;
#pragma unroll
    for (int i = threadIdx.y; i < 32; i += 8)
        t[i][threadIdx.x] = W[(size_t)(k0 + i) * Ncols + n0 + threadIdx.x];
    __syncthreads();
#pragma unroll
    for (int i = threadIdx.y; i < 32; i += 8)
        Wt[(size_t)(n0 + i) * Kdim + k0 + threadIdx.x] = t[threadIdx.x][i];
}

// ---------------------------------------------------------------------------
// tf32 mma.sync GEMM: C[m0:+128, n0:+64] = A[.,768] @ Bt[.,768]^T (+bias)
// 256 threads = 8 warps (4 M x 2 N), warp tile 32x32, K-tile 32.
// mode 0: scatter into g_qkv [3,B,H,N,64]; mode 1: row-major out [.,768].
// ---------------------------------------------------------------------------
__global__ __launch_bounds__(256, 2) void gemm_mma(const float* __restrict__ A,
                                                   const float* __restrict__ Bt,
                                                   const float* __restrict__ bias,
                                                   float* __restrict__ outp,
                                                   int Mtotal, int mode) {
    __shared__ float As[128 * AST];
    __shared__ float Bs[64 * AST];

    const int tid = threadIdx.x;
    const int lane = tid & 31, wid = tid >> 5;
    const int warpM = wid >> 1, warpN = wid & 1;
    const int g = lane >> 2, t = lane & 3;
    const int m0 = blockIdx.y * 128, n0 = blockIdx.x * 64;

    float d[2][4][4];
#pragma unroll
    for (int i = 0; i < 2; i++)
#pragma unroll
        for (int j = 0; j < 4; j++)
#pragma unroll
            for (int c = 0; c < 4; c++) d[i][j][c] = 0.f;

    for (int kt = 0; kt < 24; kt++) {
        const int k0 = kt * 32;
        // A tile: 128 x 32 (rna-rounded to tf32), 4 float4 per thread
#pragma unroll
        for (int u = 0; u < 4; u++) {
            int idx = tid + u * 256;
            int r = idx >> 3, c4 = idx & 7;
            float4 v = make_float4(0.f, 0.f, 0.f, 0.f);
            if (m0 + r < Mtotal) v = *(const float4*)(A + (size_t)(m0 + r) * DIM + k0 + c4 * 4);
            float4 w;
            w.x = __uint_as_float(f2tf32(v.x));
            w.y = __uint_as_float(f2tf32(v.y));
            w.z = __uint_as_float(f2tf32(v.z));
            w.w = __uint_as_float(f2tf32(v.w));
            *(float4*)(As + r * AST + c4 * 4) = w;
        }
        // B tile: 64 x 32, 2 float4 per thread (rows always valid)
#pragma unroll
        for (int u = 0; u < 2; u++) {
            int idx = tid + u * 256;
            int r = idx >> 3, c4 = idx & 7;
            float4 v = *(const float4*)(Bt + (size_t)(n0 + r) * DIM + k0 + c4 * 4);
            float4 w;
            w.x = __uint_as_float(f2tf32(v.x));
            w.y = __uint_as_float(f2tf32(v.y));
            w.z = __uint_as_float(f2tf32(v.z));
            w.w = __uint_as_float(f2tf32(v.w));
            *(float4*)(Bs + r * AST + c4 * 4) = w;
        }
        __syncthreads();

#pragma unroll
        for (int ks = 0; ks < 4; ks++) {
            const int kb = ks * 8;
            uint32_t af[2][4], bf[4][2];
#pragma unroll
            for (int mf = 0; mf < 2; mf++) {
                int r0 = warpM * 32 + mf * 16 + g;
                af[mf][0] = __float_as_uint(As[r0 * AST + kb + t]);
                af[mf][1] = __float_as_uint(As[(r0 + 8) * AST + kb + t]);
                af[mf][2] = __float_as_uint(As[r0 * AST + kb + t + 4]);
                af[mf][3] = __float_as_uint(As[(r0 + 8) * AST + kb + t + 4]);
            }
#pragma unroll
            for (int nf = 0; nf < 4; nf++) {
                int c0 = warpN * 32 + nf * 8 + g;
                bf[nf][0] = __float_as_uint(Bs[c0 * AST + kb + t]);
                bf[nf][1] = __float_as_uint(Bs[c0 * AST + kb + t + 4]);
            }
#pragma unroll
            for (int mf = 0; mf < 2; mf++)
#pragma unroll
                for (int nf = 0; nf < 4; nf++) mma1688(d[mf][nf], af[mf], bf[nf]);
        }
        __syncthreads();
    }

    // Epilogue: each thread owns rows {g, g+8} cols {2t, 2t+1} per fragment
#pragma unroll
    for (int mf = 0; mf < 2; mf++) {
#pragma unroll
        for (int half = 0; half < 2; half++) {
            int row = m0 + warpM * 32 + mf * 16 + g + half * 8;
            if (row >= Mtotal) continue;
            int b_ = row / SEQ, n = row - (row / SEQ) * SEQ;
#pragma unroll
            for (int nf = 0; nf < 4; nf++) {
                int col = n0 + warpN * 32 + nf * 8 + 2 * t;
                float2 w;
                w.x = d[mf][nf][half * 2 + 0] + bias[col + 0];
                w.y = d[mf][nf][half * 2 + 1] + bias[col + 1];
                if (mode == 0) {
                    int s = col / DIM;
                    int rem = col - s * DIM;
                    int h = rem >> 6, dd = rem & 63;
                    *(float2*)(g_qkv +
                        (((size_t)s * NB * NHEADS + b_ * NHEADS + h) * SEQ + n) * HD + dd) = w;
                } else {
                    *(float2*)(outp + (size_t)row * DIM + col) = w;
                }
            }
        }
    }
}

// ---------------------------------------------------------------------------
// Flash-style attention with policy-masked softmax (unchanged, known-correct).
// ---------------------------------------------------------------------------
__global__ __launch_bounds__(256) void attn_kernel(const float* __restrict__ policy) {
    extern __shared__ float sm[];
    float* Qs   = sm;
    float* Vs   = sm + 4096;
    float* KPs  = sm + 8192;
    float* vsum = sm + 8192 + 4160;
    float* pol  = vsum + 64;

    const int bh = blockIdx.y;
    const int b_ = bh / NHEADS;
    const int q0 = blockIdx.x * 64;
    const float* Qg = g_qkv + (size_t)bh * SEQ * HD;
    const float* Kg = g_qkv + (size_t)(NB * NHEADS + bh) * SEQ * HD;
    const float* Vg = g_qkv + (size_t)(2 * NB * NHEADS + bh) * SEQ * HD;
    const int tid = threadIdx.x;
    const int tx = tid & 15, ty = tid >> 4;

    for (int e = tid; e < 64 * 16; e += 256) {
        int r = e >> 4, c4 = e & 15;
        float4 v = make_float4(0.f, 0.f, 0.f, 0.f);
        if (q0 + r < SEQ) v = *(const float4*)(Qg + (size_t)(q0 + r) * HD + c4 * 4);
        *(float4*)(Qs + r * 64 + c4 * 4) = v;
    }
    if (tid < 64) vsum[tid] = 0.f;

    float mrow[4], lrow[4], Oacc[4][4];
#pragma unroll
    for (int i = 0; i < 4; i++) {
        mrow[i] = -1e30f; lrow[i] = 0.f;
#pragma unroll
        for (int j = 0; j < 4; j++) Oacc[i][j] = 0.f;
    }

    for (int kc = 0; kc < 10; kc++) {
        const int kb = kc * 64;
        __syncthreads();
        for (int e = tid; e < 64 * 16; e += 256) {
            int r = e >> 4, c4 = e & 15;
            float4 kv = make_float4(0.f, 0.f, 0.f, 0.f), vv = kv;
            if (kb + r < SEQ) {
                kv = *(const float4*)(Kg + (size_t)(kb + r) * HD + c4 * 4);
                vv = *(const float4*)(Vg + (size_t)(kb + r) * HD + c4 * 4);
            }
            float* kd = KPs + r * 65 + c4 * 4;
            kd[0] = kv.x; kd[1] = kv.y; kd[2] = kv.z; kd[3] = kv.w;
            *(float4*)(Vs + r * 64 + c4 * 4) = vv;
        }
        if (tid < 64) pol[tid] = (kb + tid < SEQ) ? policy[b_ * SEQ + kb + tid] : 0.f;
        __syncthreads();

        if (tid < 64) {
            float s = 0.f;
            for (int c = 0; c < 64; c++) s += Vs[c * 64 + tid];
            vsum[tid] += s;
        }

        float sc[4][4];
#pragma unroll
        for (int i = 0; i < 4; i++)
#pragma unroll
            for (int j = 0; j < 4; j++) sc[i][j] = 0.f;
        for (int dd = 0; dd < HD; dd++) {
            float qa[4], kk[4];
#pragma unroll
            for (int i = 0; i < 4; i++) qa[i] = Qs[(4 * ty + i) * 64 + dd];
#pragma unroll
            for (int j = 0; j < 4; j++) kk[j] = KPs[(4 * tx + j) * 65 + dd];
#pragma unroll
            for (int i = 0; i < 4; i++)
#pragma unroll
                for (int j = 0; j < 4; j++) sc[i][j] += qa[i] * kk[j];
        }
#pragma unroll
        for (int i = 0; i < 4; i++)
#pragma unroll
            for (int j = 0; j < 4; j++) {
                int key = kb + 4 * tx + j;
                sc[i][j] = (key < SEQ) ? sc[i][j] * ATT_SCALE : -1e30f;
            }

#pragma unroll
        for (int i = 0; i < 4; i++) {
            float rm = fmaxf(fmaxf(sc[i][0], sc[i][1]), fmaxf(sc[i][2], sc[i][3]));
#pragma unroll
            for (int off = 8; off; off >>= 1)
                rm = fmaxf(rm, __shfl_xor_sync(0xffffffffu, rm, off, 16));
            float nm = fmaxf(mrow[i], rm);
            float corr = __expf(mrow[i] - nm);
            mrow[i] = nm;
            int q = q0 + 4 * ty + i;
            float ls = 0.f;
#pragma unroll
            for (int j = 0; j < 4; j++) {
                int key = kb + 4 * tx + j;
                bool keep = (key < SEQ) && ((pol[4 * tx + j] > 0.5f) || (key == q));
                float p = keep ? __expf(sc[i][j] - nm) : 0.f;
                sc[i][j] = p;
                ls += p;
            }
#pragma unroll
            for (int off = 8; off; off >>= 1)
                ls += __shfl_xor_sync(0xffffffffu, ls, off, 16);
            lrow[i] = lrow[i] * corr + ls;
#pragma unroll
            for (int j = 0; j < 4; j++) Oacc[i][j] *= corr;
        }
        __syncthreads();
#pragma unroll
        for (int i = 0; i < 4; i++)
#pragma unroll
            for (int j = 0; j < 4; j++)
                KPs[(4 * ty + i) * 65 + 4 * tx + j] = sc[i][j];
        __syncthreads();

        for (int c = 0; c < 64; c++) {
            float pa[4], vb[4];
#pragma unroll
            for (int i = 0; i < 4; i++) pa[i] = KPs[(4 * ty + i) * 65 + c];
#pragma unroll
            for (int j = 0; j < 4; j++) vb[j] = Vs[c * 64 + 4 * tx + j];
#pragma unroll
            for (int i = 0; i < 4; i++)
#pragma unroll
                for (int j = 0; j < 4; j++) Oacc[i][j] += pa[i] * vb[j];
        }
    }
    __syncthreads();

    const float epsn = EPSF / (float)SEQ;
    const int h = blockIdx.y % NHEADS;
#pragma unroll
    for (int i = 0; i < 4; i++) {
        int n = q0 + 4 * ty + i;
        if (n >= SEQ) continue;
        float inv = 1.f / (lrow[i] + EPSF);
#pragma unroll
        for (int j = 0; j < 4; j++) {
            int dd = 4 * tx + j;
            g_attn[((size_t)b_ * SEQ + n) * DIM + h * HD + dd] =
                (Oacc[i][j] + epsn * vsum[dd]) * inv;
        }
    }
}

// ---------------------------------------------------------------------------
extern "C" void kernel_launch(void* const* d_in, const int* in_sizes, int n_in,
                              void* d_out, int out_size) {
    const float* x      = (const float*)d_in[0];
    const float* policy = (const float*)d_in[1];
    const float* Wqkv   = (const float*)d_in[2];
    const float* bqkv   = (const float*)d_in[3];
    const float* Wproj  = (const float*)d_in[4];
    const float* bproj  = (const float*)d_in[5];
    float* out = (float*)d_out;
    (void)in_sizes; (void)n_in; (void)out_size;

    void *p_wqkv_t = nullptr, *p_wproj_t = nullptr, *p_attn = nullptr;
    cudaGetSymbolAddress(&p_wqkv_t, g_wqkv_t);
    cudaGetSymbolAddress(&p_wproj_t, g_wproj_t);
    cudaGetSymbolAddress(&p_attn, g_attn);

    // 0) transpose weights to [N, K]
    dim3 tb(32, 8);
    transpose_w<<<dim3(NQKV / 32, DIM / 32), tb>>>(Wqkv, (float*)p_wqkv_t, DIM, NQKV);
    transpose_w<<<dim3(DIM / 32, DIM / 32), tb>>>(Wproj, (float*)p_wproj_t, DIM, DIM);

    // 1) QKV projection (tensor cores), scatter to [3,B,H,N,64]
    dim3 g1(NQKV / 64, (MROWS + 127) / 128);
    gemm_mma<<<g1, 256>>>(x, (const float*)p_wqkv_t, bqkv, nullptr, MROWS, 0);

    // 2) policy-masked flash attention (fp32)
    const int asmem = (4096 + 4096 + 4160 + 64 + 64) * 4;
    cudaFuncSetAttribute(attn_kernel, cudaFuncAttributeMaxDynamicSharedMemorySize, asmem);
    dim3 g2((SEQ + 63) / 64, NB * NHEADS);
    attn_kernel<<<g2, 256, asmem>>>(policy);

    // 3) output projection (tensor cores)
    dim3 g3(DIM / 64, (MROWS + 127) / 128);
    gemm_mma<<<g3, 256>>>((const float*)p_attn, (const float*)p_wproj_t, bproj, out, MROWS, 1);
}

// round 5
// speedup vs baseline: 2.8046x; 1.6756x over previous
#include <cuda_runtime.h>
#include <cstdint>

#define NHEADS 12
#define HD 64
#define NB 16
#define SEQ 577
#define DIM 768
#define MROWS (NB * SEQ)        // 9232
#define NQKV (3 * DIM)          // 2304
#define NBH (NB * NHEADS)       // 192
#define ATT_SCALE 0.125f
#define EPSF 1e-6f
#define AST 36                  // gemm smem stride
#define KST 68                  // attn smem stride (floats): conflict-free frag loads

// Scratch (no allocations allowed)
__device__ float g_qkv[(size_t)3 * NBH * SEQ * HD];   // [3,B,H,N,64]
__device__ float g_attn[(size_t)MROWS * DIM];         // [B*N, 768]
__device__ float g_wqkv_t[(size_t)NQKV * DIM];
__device__ float g_wproj_t[(size_t)DIM * DIM];
__device__ float g_vsum[(size_t)NBH * HD];            // per (b,h): sum_keys V

__device__ __forceinline__ uint32_t f2tf32(float x) {
    uint32_t r;
    asm("cvt.rna.tf32.f32 %0, %1;" : "=r"(r) : "f"(x));
    return r;
}
__device__ __forceinline__ void mma1688(float d[4], const uint32_t a[4], const uint32_t b[2]) {
    asm volatile(
        "mma.sync.aligned.m16n8k8.row.col.f32.tf32.tf32.f32 "
        "{%0,%1,%2,%3}, {%4,%5,%6,%7}, {%8,%9}, {%0,%1,%2,%3};"
        : "+f"(d[0]), "+f"(d[1]), "+f"(d[2]), "+f"(d[3])
        : "r"(a[0]), "r"(a[1]), "r"(a[2]), "r"(a[3]), "r"(b[0]), "r"(b[1]));
}

// ---------------------------------------------------------------------------
__global__ __launch_bounds__(256) void transpose_w(const float* __restrict__ W,
                                                   float* __restrict__ Wt,
                                                   int Kdim, int Ncols) {
    __shared__ float t[32][33];
    const int n0 = blockIdx.x * 32, k0 = blockIdx.y * 32;
#pragma unroll
    for (int i = threadIdx.y; i < 32; i += 8)
        t[i][threadIdx.x] = W[(size_t)(k0 + i) * Ncols + n0 + threadIdx.x];
    __syncthreads();
#pragma unroll
    for (int i = threadIdx.y; i < 32; i += 8)
        Wt[(size_t)(n0 + i) * Kdim + k0 + threadIdx.x] = t[threadIdx.x][i];
}

// ---------------------------------------------------------------------------
// tf32 mma.sync GEMM (unchanged from R3, validated)
// ---------------------------------------------------------------------------
__global__ __launch_bounds__(256, 2) void gemm_mma(const float* __restrict__ A,
                                                   const float* __restrict__ Bt,
                                                   const float* __restrict__ bias,
                                                   float* __restrict__ outp,
                                                   int Mtotal, int mode) {
    __shared__ float As[128 * AST];
    __shared__ float Bs[64 * AST];

    const int tid = threadIdx.x;
    const int lane = tid & 31, wid = tid >> 5;
    const int warpM = wid >> 1, warpN = wid & 1;
    const int g = lane >> 2, t = lane & 3;
    const int m0 = blockIdx.y * 128, n0 = blockIdx.x * 64;

    float d[2][4][4];
#pragma unroll
    for (int i = 0; i < 2; i++)
#pragma unroll
        for (int j = 0; j < 4; j++)
#pragma unroll
            for (int c = 0; c < 4; c++) d[i][j][c] = 0.f;

    for (int kt = 0; kt < 24; kt++) {
        const int k0 = kt * 32;
#pragma unroll
        for (int u = 0; u < 4; u++) {
            int idx = tid + u * 256;
            int r = idx >> 3, c4 = idx & 7;
            float4 v = make_float4(0.f, 0.f, 0.f, 0.f);
            if (m0 + r < Mtotal) v = *(const float4*)(A + (size_t)(m0 + r) * DIM + k0 + c4 * 4);
            float4 w;
            w.x = __uint_as_float(f2tf32(v.x));
            w.y = __uint_as_float(f2tf32(v.y));
            w.z = __uint_as_float(f2tf32(v.z));
            w.w = __uint_as_float(f2tf32(v.w));
            *(float4*)(As + r * AST + c4 * 4) = w;
        }
#pragma unroll
        for (int u = 0; u < 2; u++) {
            int idx = tid + u * 256;
            int r = idx >> 3, c4 = idx & 7;
            float4 v = *(const float4*)(Bt + (size_t)(n0 + r) * DIM + k0 + c4 * 4);
            float4 w;
            w.x = __uint_as_float(f2tf32(v.x));
            w.y = __uint_as_float(f2tf32(v.y));
            w.z = __uint_as_float(f2tf32(v.z));
            w.w = __uint_as_float(f2tf32(v.w));
            *(float4*)(Bs + r * AST + c4 * 4) = w;
        }
        __syncthreads();

#pragma unroll
        for (int ks = 0; ks < 4; ks++) {
            const int kb = ks * 8;
            uint32_t af[2][4], bf[4][2];
#pragma unroll
            for (int mf = 0; mf < 2; mf++) {
                int r0 = warpM * 32 + mf * 16 + g;
                af[mf][0] = __float_as_uint(As[r0 * AST + kb + t]);
                af[mf][1] = __float_as_uint(As[(r0 + 8) * AST + kb + t]);
                af[mf][2] = __float_as_uint(As[r0 * AST + kb + t + 4]);
                af[mf][3] = __float_as_uint(As[(r0 + 8) * AST + kb + t + 4]);
            }
#pragma unroll
            for (int nf = 0; nf < 4; nf++) {
                int c0 = warpN * 32 + nf * 8 + g;
                bf[nf][0] = __float_as_uint(Bs[c0 * AST + kb + t]);
                bf[nf][1] = __float_as_uint(Bs[c0 * AST + kb + t + 4]);
            }
#pragma unroll
            for (int mf = 0; mf < 2; mf++)
#pragma unroll
                for (int nf = 0; nf < 4; nf++) mma1688(d[mf][nf], af[mf], bf[nf]);
        }
        __syncthreads();
    }

#pragma unroll
    for (int mf = 0; mf < 2; mf++) {
#pragma unroll
        for (int half = 0; half < 2; half++) {
            int row = m0 + warpM * 32 + mf * 16 + g + half * 8;
            if (row >= Mtotal) continue;
            int b_ = row / SEQ, n = row - (row / SEQ) * SEQ;
#pragma unroll
            for (int nf = 0; nf < 4; nf++) {
                int col = n0 + warpN * 32 + nf * 8 + 2 * t;
                float2 w;
                w.x = d[mf][nf][half * 2 + 0] + bias[col + 0];
                w.y = d[mf][nf][half * 2 + 1] + bias[col + 1];
                if (mode == 0) {
                    int s = col / DIM;
                    int rem = col - s * DIM;
                    int h = rem >> 6, dd = rem & 63;
                    *(float2*)(g_qkv +
                        (((size_t)s * NBH + b_ * NHEADS + h) * SEQ + n) * HD + dd) = w;
                } else {
                    *(float2*)(outp + (size_t)row * DIM + col) = w;
                }
            }
        }
    }
}

// ---------------------------------------------------------------------------
// Per-(b,h) column sums of V: g_vsum[bh][d] = sum_keys V[key][d]
// ---------------------------------------------------------------------------
__global__ __launch_bounds__(64) void vsum_kernel() {
    const int bh = blockIdx.x;
    const float* Vg = g_qkv + (size_t)(2 * NBH + bh) * SEQ * HD;
    float s = 0.f;
    for (int k = 0; k < SEQ; k++) s += Vg[k * HD + threadIdx.x];
    g_vsum[bh * HD + threadIdx.x] = s;
}

// ---------------------------------------------------------------------------
// Tensor-core attention: Q-tile 128, 8 warps x (16q x 64keys), tf32 mma.
// Warp-local online softmax (shfl over t-quad). Policy-masked per reference.
// ---------------------------------------------------------------------------
__global__ __launch_bounds__(256, 2) void attn_mma(const float* __restrict__ policy) {
    extern __shared__ float sm[];
    float* Ks = sm;                       // 64 x KST
    float* Vs = sm + 64 * KST;            // 64 x KST
    float* Ps = sm + 128 * KST;           // 128 x KST
    float* pol = sm + 256 * KST;          // 64

    const int bh = blockIdx.y;
    const int b_ = bh / NHEADS, h = bh % NHEADS;
    const int q0 = blockIdx.x * 128;
    const float* Qg = g_qkv + (size_t)bh * SEQ * HD;
    const float* Kg = g_qkv + (size_t)(NBH + bh) * SEQ * HD;
    const float* Vg = g_qkv + (size_t)(2 * NBH + bh) * SEQ * HD;

    const int tid = threadIdx.x;
    const int lane = tid & 31, w = tid >> 5;
    const int g = lane >> 2, t = lane & 3;
    const int r0 = q0 + w * 16 + g;       // global q row for frag slots 0/2

    // Q fragments in registers for all chunks (tf32-rounded)
    uint32_t aq[8][4];
#pragma unroll
    for (int ks = 0; ks < 8; ks++) {
        int c = ks * 8 + t;
        aq[ks][0] = (r0 < SEQ)     ? f2tf32(Qg[(size_t)r0 * HD + c])           : 0u;
        aq[ks][1] = (r0 + 8 < SEQ) ? f2tf32(Qg[(size_t)(r0 + 8) * HD + c])     : 0u;
        aq[ks][2] = (r0 < SEQ)     ? f2tf32(Qg[(size_t)r0 * HD + c + 4])       : 0u;
        aq[ks][3] = (r0 + 8 < SEQ) ? f2tf32(Qg[(size_t)(r0 + 8) * HD + c + 4]) : 0u;
    }

    float mrow[2] = {-1e30f, -1e30f}, lrow[2] = {0.f, 0.f};
    float o[8][4];
#pragma unroll
    for (int nf = 0; nf < 8; nf++)
#pragma unroll
        for (int c = 0; c < 4; c++) o[nf][c] = 0.f;

    for (int kc = 0; kc < 10; kc++) {
        const int kb = kc * 64;
        __syncthreads();   // all warps done with previous Ks/Vs
        // stage K,V chunk (tf32-rounded), zeros beyond SEQ
#pragma unroll
        for (int u = 0; u < 4; u++) {
            int idx = tid + u * 256;
            int r = idx >> 4, c4 = idx & 15;
            float4 v = make_float4(0.f, 0.f, 0.f, 0.f);
            if (kb + r < SEQ) v = *(const float4*)(Kg + (size_t)(kb + r) * HD + c4 * 4);
            float4 ww;
            ww.x = __uint_as_float(f2tf32(v.x));
            ww.y = __uint_as_float(f2tf32(v.y));
            ww.z = __uint_as_float(f2tf32(v.z));
            ww.w = __uint_as_float(f2tf32(v.w));
            *(float4*)(Ks + r * KST + c4 * 4) = ww;
        }
#pragma unroll
        for (int u = 0; u < 4; u++) {
            int idx = tid + u * 256;
            int r = idx >> 4, c4 = idx & 15;
            float4 v = make_float4(0.f, 0.f, 0.f, 0.f);
            if (kb + r < SEQ) v = *(const float4*)(Vg + (size_t)(kb + r) * HD + c4 * 4);
            float4 ww;
            ww.x = __uint_as_float(f2tf32(v.x));
            ww.y = __uint_as_float(f2tf32(v.y));
            ww.z = __uint_as_float(f2tf32(v.z));
            ww.w = __uint_as_float(f2tf32(v.w));
            *(float4*)(Vs + r * KST + c4 * 4) = ww;
        }
        if (tid < 64) pol[tid] = (kb + tid < SEQ) ? policy[b_ * SEQ + kb + tid] : 0.f;
        __syncthreads();

        // S = Q K^T  (16q x 64keys per warp)
        float s[8][4];
#pragma unroll
        for (int nf = 0; nf < 8; nf++)
#pragma unroll
            for (int c = 0; c < 4; c++) s[nf][c] = 0.f;
#pragma unroll
        for (int ks = 0; ks < 8; ks++) {
            const int kcol = ks * 8;
#pragma unroll
            for (int nf = 0; nf < 8; nf++) {
                uint32_t bf[2];
                bf[0] = __float_as_uint(Ks[(nf * 8 + g) * KST + kcol + t]);
                bf[1] = __float_as_uint(Ks[(nf * 8 + g) * KST + kcol + t + 4]);
                mma1688(s[nf], aq[ks], bf);
            }
        }

        // scale + pad-mask into logits
#pragma unroll
        for (int nf = 0; nf < 8; nf++)
#pragma unroll
            for (int c = 0; c < 4; c++) {
                int key = kb + nf * 8 + 2 * t + (c & 1);
                s[nf][c] = (key < SEQ) ? s[nf][c] * ATT_SCALE : -1e30f;
            }

        // warp-local online softmax (rows g and g+8)
#pragma unroll
        for (int half = 0; half < 2; half++) {
            const int qglob = r0 + 8 * half;
            float rm = -1e30f;
#pragma unroll
            for (int nf = 0; nf < 8; nf++)
                rm = fmaxf(rm, fmaxf(s[nf][half * 2], s[nf][half * 2 + 1]));
            rm = fmaxf(rm, __shfl_xor_sync(0xffffffffu, rm, 1));
            rm = fmaxf(rm, __shfl_xor_sync(0xffffffffu, rm, 2));
            float nm = fmaxf(mrow[half], rm);
            float corr = __expf(mrow[half] - nm);
            mrow[half] = nm;
            float ls = 0.f;
#pragma unroll
            for (int nf = 0; nf < 8; nf++) {
#pragma unroll
                for (int c = 0; c < 2; c++) {
                    int kl = nf * 8 + 2 * t + c;
                    int key = kb + kl;
                    bool keep = (pol[kl] > 0.5f) || (key == qglob);
                    float p = keep ? __expf(s[nf][half * 2 + c] - nm) : 0.f;
                    s[nf][half * 2 + c] = p;
                    ls += p;
                }
            }
            ls += __shfl_xor_sync(0xffffffffu, ls, 1);
            ls += __shfl_xor_sync(0xffffffffu, ls, 2);
            lrow[half] = lrow[half] * corr + ls;
#pragma unroll
            for (int nf = 0; nf < 8; nf++) {
                o[nf][half * 2] *= corr;
                o[nf][half * 2 + 1] *= corr;
            }
        }

        // P -> smem (own rows only; same-warp STS->LDS needs no barrier)
#pragma unroll
        for (int nf = 0; nf < 8; nf++) {
#pragma unroll
            for (int half = 0; half < 2; half++) {
                float2 pv;
                pv.x = __uint_as_float(f2tf32(s[nf][half * 2]));
                pv.y = __uint_as_float(f2tf32(s[nf][half * 2 + 1]));
                *(float2*)(Ps + (w * 16 + g + 8 * half) * KST + nf * 8 + 2 * t) = pv;
            }
        }

        // O += P V  (B-frag: V^T[d][key] read from row-major Vs)
#pragma unroll
        for (int ks = 0; ks < 8; ks++) {
            uint32_t ap[4];
            const int kcol = ks * 8;
            ap[0] = __float_as_uint(Ps[(w * 16 + g) * KST + kcol + t]);
            ap[1] = __float_as_uint(Ps[(w * 16 + g + 8) * KST + kcol + t]);
            ap[2] = __float_as_uint(Ps[(w * 16 + g) * KST + kcol + t + 4]);
            ap[3] = __float_as_uint(Ps[(w * 16 + g + 8) * KST + kcol + t + 4]);
#pragma unroll
            for (int nf = 0; nf < 8; nf++) {
                uint32_t bf[2];
                bf[0] = __float_as_uint(Vs[(kcol + t) * KST + nf * 8 + g]);
                bf[1] = __float_as_uint(Vs[(kcol + t + 4) * KST + nf * 8 + g]);
                mma1688(o[nf], ap, bf);
            }
        }
    }

    // epilogue
    const float epsn = EPSF / (float)SEQ;
#pragma unroll
    for (int half = 0; half < 2; half++) {
        int qglob = r0 + 8 * half;
        if (qglob >= SEQ) continue;
        float inv = 1.f / (lrow[half] + EPSF);
        int n = qglob;
#pragma unroll
        for (int nf = 0; nf < 8; nf++) {
            int dd = nf * 8 + 2 * t;
            float2 vs = *(const float2*)(g_vsum + bh * HD + dd);
            float2 ww;
            ww.x = (o[nf][half * 2] + epsn * vs.x) * inv;
            ww.y = (o[nf][half * 2 + 1] + epsn * vs.y) * inv;
            *(float2*)(g_attn + ((size_t)b_ * SEQ + n) * DIM + h * HD + dd) = ww;
        }
    }
}

// ---------------------------------------------------------------------------
extern "C" void kernel_launch(void* const* d_in, const int* in_sizes, int n_in,
                              void* d_out, int out_size) {
    const float* x      = (const float*)d_in[0];
    const float* policy = (const float*)d_in[1];
    const float* Wqkv   = (const float*)d_in[2];
    const float* bqkv   = (const float*)d_in[3];
    const float* Wproj  = (const float*)d_in[4];
    const float* bproj  = (const float*)d_in[5];
    float* out = (float*)d_out;
    (void)in_sizes; (void)n_in; (void)out_size;

    void *p_wqkv_t = nullptr, *p_wproj_t = nullptr, *p_attn = nullptr;
    cudaGetSymbolAddress(&p_wqkv_t, g_wqkv_t);
    cudaGetSymbolAddress(&p_wproj_t, g_wproj_t);
    cudaGetSymbolAddress(&p_attn, g_attn);

    dim3 tb(32, 8);
    transpose_w<<<dim3(NQKV / 32, DIM / 32), tb>>>(Wqkv, (float*)p_wqkv_t, DIM, NQKV);
    transpose_w<<<dim3(DIM / 32, DIM / 32), tb>>>(Wproj, (float*)p_wproj_t, DIM, DIM);

    // 1) QKV projection (tensor cores), scatter to [3,B,H,N,64]
    dim3 g1(NQKV / 64, (MROWS + 127) / 128);
    gemm_mma<<<g1, 256>>>(x, (const float*)p_wqkv_t, bqkv, nullptr, MROWS, 0);

    // 1b) per-(b,h) V column sums
    vsum_kernel<<<NBH, 64>>>();

    // 2) tensor-core policy-masked flash attention
    const int asmem = (256 * KST + 64) * 4;   // ~69.9 KB
    cudaFuncSetAttribute(attn_mma, cudaFuncAttributeMaxDynamicSharedMemorySize, asmem);
    dim3 g2((SEQ + 127) / 128, NBH);
    attn_mma<<<g2, 256, asmem>>>(policy);

    // 3) output projection (tensor cores)
    dim3 g3(DIM / 64, (MROWS + 127) / 128);
    gemm_mma<<<g3, 256>>>((const float*)p_attn, (const float*)p_wproj_t, bproj, out, MROWS, 1);
}